// round 5
// baseline (speedup 1.0000x reference)
#include <cuda_runtime.h>
#include <cstdint>

// CenterLoss collapses: mask is one-hot(labels) -> only B entries of the
// [B, C] distance matrix survive; clip() turns the other B*(C-1) zeros into
// the closed-form constant B*(C-1)*1e-12. No GEMM.
//
// All reduction levels use the same packed-u64 trick:
//     bits [56,64): arrival count     bits [0,56): 2^32 fixed-point sum
// Integer atomic adds are exactly associative -> bit-deterministic; the op
// that completes the count *returns* the finished total (no fence, no
// counter, no re-read).
//   L0: 8 warps -> shared u64        (last warp holds block total)
//   L1: 16 blocks -> 1 of 8 padded global slots (parallel LTS partitions)
//   L2: 8 slots -> final accumulator (completer writes out + resets)

#define CL_BATCH 1024
#define CL_FEAT  128
#define CL_NUMC  100000

#define CL_THREADS 256
#define CL_BLOCKS  (CL_BATCH / 8)       // 128
#define CL_NSLOTS  8
#define CL_BLKS_PER_SLOT (CL_BLOCKS / CL_NSLOTS)   // 16

#define CL_FP_SCALE  4294967296.0       // 2^32
#define CL_CNT_UNIT  (1ULL << 56)
#define CL_SUM_MASK  (CL_CNT_UNIT - 1ULL)

struct PaddedAcc { unsigned long long v; unsigned long long pad[31]; }; // 256B
__device__ PaddedAcc g_cl_slot[CL_NSLOTS];   // zero-initialized
__device__ PaddedAcc g_cl_final;

__global__ void __launch_bounds__(CL_THREADS)
center_loss_fused(const float* __restrict__ x,
                  const int* __restrict__ labels,
                  const float* __restrict__ centers,
                  float* __restrict__ out)
{
    const int tid     = threadIdx.x;
    const int lane    = tid & 31;
    const int warpInB = tid >> 5;                      // 0..7
    const int sample  = blockIdx.x * 8 + warpInB;      // 0..1023

    __shared__ unsigned long long s_acc;
    if (tid == 0) s_acc = 0ULL;
    __syncthreads();                      // cheap: before any memory waits

    // Broadcast label load (1 request/warp), then gathered center row.
    const int lbl = labels[sample];

    const float4 xv = reinterpret_cast<const float4*>(x + (size_t)sample * CL_FEAT)[lane];
    const float4 cv = reinterpret_cast<const float4*>(centers + (size_t)lbl * CL_FEAT)[lane];

    // ||x||^2 + ||c||^2 - 2 x.c, expanded like the reference.
    float p = 0.f;
    p += xv.x * xv.x + cv.x * cv.x - 2.f * xv.x * cv.x;
    p += xv.y * xv.y + cv.y * cv.y - 2.f * xv.y * cv.y;
    p += xv.z * xv.z + cv.z * cv.z - 2.f * xv.z * cv.z;
    p += xv.w * xv.w + cv.w * cv.w - 2.f * xv.w * cv.w;

    #pragma unroll
    for (int off = 16; off > 0; off >>= 1)
        p += __shfl_xor_sync(0xFFFFFFFFu, p, off);

    if (lane == 0) {
        const float clipped = fminf(fmaxf(p, 1e-12f), 1e12f);
        const unsigned long long q =
            (unsigned long long)((double)clipped * CL_FP_SCALE + 0.5)
            + CL_CNT_UNIT;

        // L0: shared packed accumulate across the 8 warps (no barrier).
        unsigned long long nowB = atomicAdd(&s_acc, q) + q;
        if ((nowB >> 56) == 8ULL) {
            // Last warp of this block: nowB holds the exact block total.
            const unsigned long long qS = (nowB & CL_SUM_MASK) + CL_CNT_UNIT;

            // L1: one of 8 padded slots (16 blocks each, parallel in L2).
            const int slot = blockIdx.x & (CL_NSLOTS - 1);
            unsigned long long nowS = atomicAdd(&g_cl_slot[slot].v, qS) + qS;

            if ((nowS >> 56) == (unsigned long long)CL_BLKS_PER_SLOT) {
                // L2: slot completer forwards to the final accumulator.
                const unsigned long long qF = (nowS & CL_SUM_MASK) + CL_CNT_UNIT;
                unsigned long long nowF = atomicAdd(&g_cl_final.v, qF) + qF;

                if ((nowF >> 56) == (unsigned long long)CL_NSLOTS) {
                    double total = (double)(nowF & CL_SUM_MASK) / CL_FP_SCALE
                                 + (double)CL_BATCH * (double)(CL_NUMC - 1) * 1e-12;
                    out[0] = (float)(total / (double)CL_BATCH);
                    // Reset for the next graph replay (all adds have
                    // completed: every count reached its target).
                    #pragma unroll
                    for (int i = 0; i < CL_NSLOTS; ++i) g_cl_slot[i].v = 0ULL;
                    g_cl_final.v = 0ULL;
                }
            }
        }
    }
}

extern "C" void kernel_launch(void* const* d_in, const int* in_sizes, int n_in,
                              void* d_out, int out_size)
{
    const float* x       = (const float*)d_in[0];
    const int*   labels  = (const int*)d_in[1];
    const float* centers = (const float*)d_in[2];
    float*       out     = (float*)d_out;

    center_loss_fused<<<CL_BLOCKS, CL_THREADS>>>(x, labels, centers, out);
}

// round 7
// speedup vs baseline: 1.1192x; 1.1192x over previous
#include <cuda_runtime.h>
#include <cstdint>

// CenterLoss collapses: mask is one-hot(labels) -> only B entries of the
// [B, C] distance matrix survive; clip() turns the other B*(C-1) zeros into
// the closed-form constant B*(C-1)*1e-12. No GEMM.
//
// Structure = R4 (best measured kernel): 128 blocks x 256 thr, one sample
// per warp, smem stage + single packed count|sum u64 global atomic.
//   bits [56,64): block arrival count   bits [0,56): 2^32 fixed-point sum
// Integer adds are exactly associative -> bit-deterministic; the block whose
// add completes the count receives the finished total in the return value.
//
// Warp reduction: redux.sync.add.u32 (sm_80+, works on plain sm_100 target)
// over 2^22 fixed-point lane partials — one HW instruction instead of the
// 5-step shuffle/FADD dependency ladder. Integer -> exactly associative ->
// deterministic. Quantization ~2^-23/lane: rel err ~1e-10 vs 1e-3 gate.

#define CL_BATCH 1024
#define CL_FEAT  128
#define CL_NUMC  100000

#define CL_THREADS 256
#define CL_BLOCKS  (CL_BATCH / 8)     // 128 blocks, 8 warps = 8 samples each

#define CL_LANE_SCALE 4194304.0f      // 2^22 (per-lane fixed point)
#define CL_LANE_INV   (1.0 / 4194304.0)

#define CL_FP_SCALE 4294967296.0      // 2^32 (cross-block fixed point)
#define CL_COUNT_UNIT (1ULL << 56)
#define CL_SUM_MASK  (CL_COUNT_UNIT - 1ULL)

__device__ unsigned long long g_cl_accum = 0ULL;

__device__ __forceinline__ unsigned int warp_sum_u32(unsigned int v)
{
    // Hardware warp integer reduction (sm_80+): single instruction,
    // exactly associative -> deterministic.
    unsigned int r;
    asm volatile("redux.sync.add.u32 %0, %1, 0xffffffff;"
                 : "=r"(r) : "r"(v));
    return r;
}

__global__ void __launch_bounds__(CL_THREADS)
center_loss_fused(const float* __restrict__ x,
                  const int* __restrict__ labels,
                  const float* __restrict__ centers,
                  float* __restrict__ out)
{
    const int tid     = threadIdx.x;
    const int lane    = tid & 31;
    const int warpInB = tid >> 5;                      // 0..7
    const int sample  = blockIdx.x * 8 + warpInB;      // 0..1023

    // Broadcast label load (all lanes same address -> 1 request).
    const int lbl = labels[sample];

    // 128 floats per row = 32 lanes x float4.
    const float4 xv = reinterpret_cast<const float4*>(x + (size_t)sample * CL_FEAT)[lane];
    const float4 cv = reinterpret_cast<const float4*>(centers + (size_t)lbl * CL_FEAT)[lane];

    // ||x||^2 + ||c||^2 - 2 x.c, expanded like the reference.
    float p = 0.f;
    p += xv.x * xv.x + cv.x * cv.x - 2.f * xv.x * cv.x;
    p += xv.y * xv.y + cv.y * cv.y - 2.f * xv.y * cv.y;
    p += xv.z * xv.z + cv.z * cv.z - 2.f * xv.z * cv.z;
    p += xv.w * xv.w + cv.w * cv.w - 2.f * xv.w * cv.w;

    // 2^22 fixed point (float->uint saturates tiny negative rounding to 0),
    // then a single-instruction exact warp sum.
    const unsigned int usum = warp_sum_u32(__float2uint_rn(p * CL_LANE_SCALE));

    // Per-warp clipped value -> smem, fixed-order block sum.
    __shared__ float sm[8];
    if (lane == 0) {
        const float d = (float)((double)usum * CL_LANE_INV);
        sm[warpInB] = fminf(fmaxf(d, 1e-12f), 1e12f);
    }
    __syncthreads();

    if (tid == 0) {
        float bp = 0.f;
        #pragma unroll
        for (int i = 0; i < 8; ++i) bp += sm[i];              // fixed order

        unsigned long long q =
            (unsigned long long)((double)bp * CL_FP_SCALE + 0.5)
            + CL_COUNT_UNIT;

        unsigned long long now = atomicAdd(&g_cl_accum, q) + q;

        if ((now >> 56) == (unsigned long long)CL_BLOCKS) {
            // This block completed the sum; 'now' holds the exact total.
            double total = (double)(now & CL_SUM_MASK) / CL_FP_SCALE
                         + (double)CL_BATCH * (double)(CL_NUMC - 1) * 1e-12;
            out[0] = (float)(total / (double)CL_BATCH);
            g_cl_accum = 0ULL;        // reset for next graph replay
        }
    }
}

extern "C" void kernel_launch(void* const* d_in, const int* in_sizes, int n_in,
                              void* d_out, int out_size)
{
    const float* x       = (const float*)d_in[0];
    const int*   labels  = (const int*)d_in[1];
    const float* centers = (const float*)d_in[2];
    float*       out     = (float*)d_out;

    center_loss_fused<<<CL_BLOCKS, CL_THREADS>>>(x, labels, centers, out);
}